// round 16
// baseline (speedup 1.0000x reference)
#include <cuda_runtime.h>
#include <cuda_bf16.h>
#include <math.h>
#include <stdint.h>

#define D_MODEL 512
#define F_FF    2048
#define N_EXP   8
#define N_TOK   8192
#define N_ASSIGN (N_TOK * 2)
#define NT_TILES 160
#define BM 128
#define BN 128
#define BK 32            // K elems per stage (each row carries hi+lo limbs)
#define LDAB 144         // smem row: 64B hi | 64B lo | 16B pad

#define SA_ST (BM * LDAB)                 // 18432
#define STOK_OFF  (6 * SA_ST)             // 110592 (3 A stages + 3 B stages)
#define SW_OFF    (STOK_OFF + 512)
#define SBIAS_OFF (SW_OFF + 512)
#define SMEM_BYTES (SBIAS_OFF + 512)      // 112128

// prep block partition
#define NB_GATE 1024
#define NB_W1T  8192
#define NB_W2T  8192
#define KSPLIT  2

#define OUT_LOGITS ((size_t)N_TOK * D_MODEL)
#define OUT_PROBS  (OUT_LOGITS + (size_t)N_TOK * N_EXP)
#define OUT_Z      (OUT_PROBS + (size_t)N_TOK * N_EXP)
#define OUT_LB     (OUT_Z + 1)
#define OUT_LOAD   (OUT_LB + 1)
#define OUT_CNT    (OUT_LOAD + N_EXP)

// ---------------- static scratch ----------------
__device__ __nv_bfloat16 g_tok_hi[N_TOK * D_MODEL];
__device__ __nv_bfloat16 g_tok_lo[N_TOK * D_MODEL];
__device__ __nv_bfloat16 g_w1T_hi[N_EXP * F_FF * D_MODEL];   // [E, F, D] K-major
__device__ __nv_bfloat16 g_w1T_lo[N_EXP * F_FF * D_MODEL];
__device__ __nv_bfloat16 g_w2T_hi[N_EXP * D_MODEL * F_FF];   // [E, D, F] K-major
__device__ __nv_bfloat16 g_w2T_lo[N_EXP * D_MODEL * F_FF];
__device__ __nv_bfloat16 g_hid_hi[(N_ASSIGN + BM) * F_FF];
__device__ __nv_bfloat16 g_hid_lo[(N_ASSIGN + BM) * F_FF];
__device__ int   g_tok[N_ASSIGN + BM];
__device__ float g_wass[N_ASSIGN + BM];   // combine weight per assignment slot
__device__ int   g_topk_idx[N_ASSIGN];
__device__ float g_topk_w[N_ASSIGN];
__device__ int   g_cnt[N_EXP];
__device__ int   g_cursor[N_EXP];
__device__ float g_zsum;
__device__ float g_loadsum[N_EXP];
__device__ int   g_tile_e[NT_TILES];
__device__ int   g_tile_p0[NT_TILES];
__device__ int   g_tile_rows[NT_TILES];

// ---------------- PTX helpers (baseline ISA only) ----------------
__device__ __forceinline__ uint32_t smem_u32(const void* p) {
    uint32_t a;
    asm("{ .reg .u64 t; cvta.to.shared.u64 t, %1; cvt.u32.u64 %0, t; }" : "=r"(a) : "l"(p));
    return a;
}
#define CP_ASYNC16(dst, src) \
    asm volatile("cp.async.cg.shared.global [%0], [%1], 16;" :: "r"(dst), "l"(src) : "memory")
#define CP_COMMIT() asm volatile("cp.async.commit_group;" ::: "memory")
#define CP_WAIT1()  asm volatile("cp.async.wait_group 1;" ::: "memory")
#define CP_WAIT0()  asm volatile("cp.async.wait_group 0;" ::: "memory")

__device__ __forceinline__ void ldsm_x4(uint32_t addr, uint32_t& r0, uint32_t& r1,
                                        uint32_t& r2, uint32_t& r3) {
    asm volatile("ldmatrix.sync.aligned.m8n8.x4.shared.b16 {%0,%1,%2,%3}, [%4];"
        : "=r"(r0), "=r"(r1), "=r"(r2), "=r"(r3) : "r"(addr));
}
__device__ __forceinline__ void mma_bf16(float* d, const uint32_t* a,
                                         uint32_t b0, uint32_t b1) {
    asm volatile(
        "mma.sync.aligned.m16n8k16.row.col.f32.bf16.bf16.f32 "
        "{%0,%1,%2,%3}, {%4,%5,%6,%7}, {%8,%9}, {%0,%1,%2,%3};"
        : "+f"(d[0]), "+f"(d[1]), "+f"(d[2]), "+f"(d[3])
        : "r"(a[0]), "r"(a[1]), "r"(a[2]), "r"(a[3]), "r"(b0), "r"(b1));
}
// fast gelu via MUFU ex2/rcp; rel err ~1e-6
__device__ __forceinline__ float gelu_f(float x) {
    const float c = 0.7978845608028654f;
    float u = c * (x + 0.044715f * x * x * x);
    float e = __expf(2.0f * u);
    float t = 1.0f - __fdividef(2.0f, e + 1.0f);
    return 0.5f * x * (1.0f + t);
}

// ---------------- init ----------------
__global__ void init_kernel() {
    int t = threadIdx.x;
    if (t < N_EXP) { g_cnt[t] = 0; g_loadsum[t] = 0.0f; }
    if (t == 0) g_zsum = 0.0f;
}

// ---------------- shared transpose+split body ----------------
__device__ __forceinline__ void transpose_split_part(
    float (*tile)[33], const float* __restrict__ in,
    __nv_bfloat16* __restrict__ out_hi, __nv_bfloat16* __restrict__ out_lo,
    int R, int C, int e, int c0, int r0, int tx, int ty)
{
    const float* src = in + (size_t)e * R * C;
    #pragma unroll
    for (int i = ty; i < 32; i += 8)
        tile[i][tx] = src[(size_t)(r0 + i) * C + c0 + tx];
    __syncthreads();
    __nv_bfloat16* dh = out_hi + (size_t)e * R * C;
    __nv_bfloat16* dl = out_lo + (size_t)e * R * C;
    #pragma unroll
    for (int i = ty; i < 32; i += 8) {
        float v = tile[tx][i];
        __nv_bfloat16 h = __float2bfloat16(v);
        __nv_bfloat16 l = __float2bfloat16(v - __bfloat162float(h));
        dh[(size_t)(c0 + i) * R + r0 + tx] = h;
        dl[(size_t)(c0 + i) * R + r0 + tx] = l;
    }
}

// ================ prep: gating(+stats) + token split + both weight transposes ========
__global__ __launch_bounds__(256) void prep_kernel(
    const float* __restrict__ tokens, const float* __restrict__ gate_w,
    const float* __restrict__ w1, const float* __restrict__ w2,
    float* __restrict__ out)
{
    __shared__ __align__(16) char sbuf[16384];
    __shared__ float s_load[N_EXP];
    __shared__ int   s_cnt[N_EXP];
    __shared__ float s_z;
    int b = blockIdx.x;
    int t = threadIdx.x;

    if (b >= NB_GATE) {
        float (*tile)[33] = (float(*)[33])sbuf;
        int tx = t & 31, ty = t >> 5;
        if (b < NB_GATE + NB_W1T) {
            int idx = b - NB_GATE;
            int e = idx >> 10, rem = idx & 1023;
            int c0 = (rem & 63) * 32, r0 = (rem >> 6) * 32;
            transpose_split_part(tile, w1, g_w1T_hi, g_w1T_lo, D_MODEL, F_FF, e, c0, r0, tx, ty);
        } else {
            int idx = b - NB_GATE - NB_W1T;
            int e = idx >> 10, rem = idx & 1023;
            int c0 = (rem & 15) * 32, r0 = (rem >> 4) * 32;
            transpose_split_part(tile, w2, g_w2T_hi, g_w2T_lo, F_FF, D_MODEL, e, c0, r0, tx, ty);
        }
        return;
    }

    float* gwT = (float*)sbuf;   // [8][512]
    for (int i = t; i < D_MODEL * N_EXP; i += 256) {
        int d = i >> 3, e = i & 7;
        gwT[e * 512 + d] = gate_w[i];
    }
    if (t < N_EXP) { s_load[t] = 0.0f; s_cnt[t] = 0; }
    if (t == 0) s_z = 0.0f;
    __syncthreads();

    int n0 = b * 8;
    {
        const float4* src = (const float4*)(tokens + (size_t)n0 * D_MODEL);
        size_t obase = (size_t)n0 * D_MODEL;
        for (int i = t; i < 1024; i += 256) {
            float4 v = src[i];
            __nv_bfloat16 h0 = __float2bfloat16(v.x), h1 = __float2bfloat16(v.y);
            __nv_bfloat16 h2 = __float2bfloat16(v.z), h3 = __float2bfloat16(v.w);
            __nv_bfloat16 l0 = __float2bfloat16(v.x - __bfloat162float(h0));
            __nv_bfloat16 l1 = __float2bfloat16(v.y - __bfloat162float(h1));
            __nv_bfloat16 l2 = __float2bfloat16(v.z - __bfloat162float(h2));
            __nv_bfloat16 l3 = __float2bfloat16(v.w - __bfloat162float(h3));
            __nv_bfloat162 ph0, ph1, pl0, pl1;
            ph0.x = h0; ph0.y = h1; ph1.x = h2; ph1.y = h3;
            pl0.x = l0; pl0.y = l1; pl1.x = l2; pl1.y = l3;
            ((__nv_bfloat162*)(g_tok_hi + obase))[2*i]   = ph0;
            ((__nv_bfloat162*)(g_tok_hi + obase))[2*i+1] = ph1;
            ((__nv_bfloat162*)(g_tok_lo + obase))[2*i]   = pl0;
            ((__nv_bfloat162*)(g_tok_lo + obase))[2*i+1] = pl1;
        }
    }

    int warp = t >> 5, lane = t & 31;
    int n = n0 + warp;
    const float* x = tokens + (size_t)n * D_MODEL;

    float acc[8] = {0.f,0.f,0.f,0.f,0.f,0.f,0.f,0.f};
    for (int d = lane; d < D_MODEL; d += 32) {
        float xv = x[d];
        #pragma unroll
        for (int e = 0; e < 8; e++) acc[e] = fmaf(xv, gwT[e * 512 + d], acc[e]);
    }
    #pragma unroll
    for (int e = 0; e < 8; e++) {
        #pragma unroll
        for (int o = 16; o; o >>= 1)
            acc[e] += __shfl_down_sync(0xffffffffu, acc[e], o);
    }

    if (lane == 0) {
        float m = acc[0];
        #pragma unroll
        for (int e = 1; e < 8; e++) m = fmaxf(m, acc[e]);
        float p[8], s = 0.0f;
        #pragma unroll
        for (int e = 0; e < 8; e++) { p[e] = expf(acc[e] - m); s += p[e]; }
        float inv = 1.0f / s;
        #pragma unroll
        for (int e = 0; e < 8; e++) p[e] *= inv;

        float* gl = out + OUT_LOGITS + (size_t)n * N_EXP;
        float* pr = out + OUT_PROBS  + (size_t)n * N_EXP;
        #pragma unroll
        for (int e = 0; e < 8; e++) { gl[e] = acc[e]; pr[e] = p[e]; }

        float lse = m + logf(s);
        atomicAdd(&s_z, lse * lse);
        #pragma unroll
        for (int e = 0; e < 8; e++) atomicAdd(&s_load[e], p[e]);

        int i0 = 0; float m0 = p[0];
        #pragma unroll
        for (int e = 1; e < 8; e++) if (p[e] > m0) { m0 = p[e]; i0 = e; }
        int i1 = (i0 == 0) ? 1 : 0; float m1 = p[i1];
        #pragma unroll
        for (int e = 0; e < 8; e++)
            if (e != i0 && p[e] > m1) { m1 = p[e]; i1 = e; }
        float ws = m0 + m1;
        g_topk_idx[2 * n]     = i0;
        g_topk_idx[2 * n + 1] = i1;
        g_topk_w[2 * n]       = m0 / ws;
        g_topk_w[2 * n + 1]   = m1 / ws;
        atomicAdd(&s_cnt[i0], 1);
        atomicAdd(&s_cnt[i1], 1);
    }
    __syncthreads();
    if (t < N_EXP) {
        atomicAdd(&g_cnt[t], s_cnt[t]);
        atomicAdd(&g_loadsum[t], s_load[t]);
    }
    if (t == 0) atomicAdd(&g_zsum, s_z);
}

// ---------------- finalize ----------------
__global__ void finalize_kernel(float* __restrict__ out) {
    if (threadIdx.x != 0) return;
    int off = 0;
    float lb = 0.0f;
    int tcount = 0;
    for (int e = 0; e < N_EXP; e++) {
        g_cursor[e] = off;
        int cnt = g_cnt[e];
        float load = g_loadsum[e] / (float)N_TOK;
        out[OUT_LOAD + e] = load;
        out[OUT_CNT + e]  = (float)cnt;
        lb += ((float)cnt / (float)N_ASSIGN) * load;
        for (int r = 0; r < cnt; r += BM) {
            g_tile_e[tcount]    = e;
            g_tile_p0[tcount]   = off + r;
            int rem = cnt - r;
            g_tile_rows[tcount] = rem < BM ? rem : BM;
            tcount++;
        }
        off += cnt;
    }
    for (int i = tcount; i < NT_TILES; i++) g_tile_rows[i] = 0;
    out[OUT_LB] = (float)N_EXP * lb;
    out[OUT_Z]  = g_zsum / (float)N_TOK;
}

// ---------------- scatter (also records per-assignment weight) ----------------
__global__ void scatter_kernel() {
    int n = blockIdx.x * blockDim.x + threadIdx.x;
    if (n >= N_TOK) return;
    #pragma unroll
    for (int k = 0; k < 2; k++) {
        int e = g_topk_idx[2 * n + k];
        int pos = atomicAdd(&g_cursor[e], 1);
        g_tok[pos]  = n;
        g_wass[pos] = g_topk_w[2 * n + k];
    }
}

// =============== fused-limb warp-MMA GEMMs ===============
// CTA 128x128, 8 warps 2(M)x4(N), warp tile 64x32. BK=32/stage, rows hi|lo|pad.

// GEMM1: hidden = gelu(gather(tokens) @ w1T^T + b1) -> split bf16 hi/lo
__global__ __launch_bounds__(256, 2) void gemm1_mma(const float* __restrict__ b1) {
    int tile = blockIdx.y;
    int rows = g_tile_rows[tile];
    if (rows == 0) return;
    int e = g_tile_e[tile], p0 = g_tile_p0[tile];
    int c0 = blockIdx.x * BN;

    extern __shared__ char dyn[];
    int*   s_tok  = (int*)(dyn + STOK_OFF);
    float* s_bias = (float*)(dyn + SBIAS_OFF);

    int t = threadIdx.x, wid = t >> 5, lane = t & 31;
    if (t < BM) {
        int rr = (t < rows) ? t : (rows - 1);
        s_tok[t]  = g_tok[p0 + rr];
        s_bias[t] = b1[(size_t)e * F_FF + c0 + t];
    }
    __syncthreads();

    uint32_t sb = smem_u32(dyn);
    uint32_t sA[3] = {sb, sb + SA_ST, sb + 2 * SA_ST};
    uint32_t sB[3] = {sb + 3 * SA_ST, sb + 4 * SA_ST, sb + 5 * SA_ST};

    auto loadStage = [&](int kt, int st) {
        int kk = kt * BK;
        #pragma unroll
        for (int it = 0; it < 4; it++) {
            int idx = t + it * 256;
            int row = idx >> 3, c = idx & 7;
            const __nv_bfloat16* src = (c < 4)
                ? g_tok_hi + (size_t)s_tok[row] * D_MODEL + kk + c * 8
                : g_tok_lo + (size_t)s_tok[row] * D_MODEL + kk + (c - 4) * 8;
            CP_ASYNC16(sA[st] + row * LDAB + ((c < 4) ? c * 16 : 64 + (c - 4) * 16), src);
        }
        const __nv_bfloat16* Bh = g_w1T_hi + ((size_t)e * F_FF + c0) * D_MODEL + kk;
        const __nv_bfloat16* Bl = g_w1T_lo + ((size_t)e * F_FF + c0) * D_MODEL + kk;
        #pragma unroll
        for (int it = 0; it < 4; it++) {
            int idx = t + it * 256;
            int row = idx >> 3, c = idx & 7;
            const __nv_bfloat16* src = (c < 4)
                ? Bh + (size_t)row * D_MODEL + c * 8
                : Bl + (size_t)row * D_MODEL + (c - 4) * 8;
            CP_ASYNC16(sB[st] + row * LDAB + ((c < 4) ? c * 16 : 64 + (c - 4) * 16), src);
        }
        CP_COMMIT();
    };

    int wm = (wid >> 2) * 64, wn = (wid & 3) * 32;
    uint32_t aOff = (uint32_t)((wm + (lane & 15)) * LDAB + (lane >> 4) * 16);
    uint32_t bOff = (uint32_t)((wn + (lane & 15)) * LDAB + (lane >> 4) * 16);

    float acc[4][4][4];
    #pragma unroll
    for (int i = 0; i < 4; i++)
        #pragma unroll
        for (int j = 0; j < 4; j++)
            #pragma unroll
            for (int r = 0; r < 4; r++) acc[i][j][r] = 0.0f;

    const int KT = D_MODEL / BK;   // 16
    loadStage(0, 0);
    loadStage(1, 1);
    #pragma unroll 1
    for (int kt = 0; kt < KT; kt++) {
        if (kt + 1 < KT) { CP_WAIT1(); } else { CP_WAIT0(); }
        __syncthreads();
        if (kt + 2 < KT) loadStage(kt + 2, (kt + 2) % 3);
        int st = kt % 3;
        uint32_t aB = sA[st] + aOff, bB = sB[st] + bOff;

        #pragma unroll
        for (int j = 0; j < 2; j++) {          // k16 sub-chunks
            uint32_t ah[4][4], al[4][4], bh[2][4], bl[2][4];
            #pragma unroll
            for (int mt = 0; mt < 4; mt++)
                ldsm_x4(aB + mt * 16 * LDAB + j * 32,
                        ah[mt][0], ah[mt][1], ah[mt][2], ah[mt][3]);
            #pragma unroll
            for (int p = 0; p < 2; p++)
                ldsm_x4(bB + p * 16 * LDAB + j * 32,
                        bh[p][0], bh[p][1], bh[p][2], bh[p][3]);
            #pragma unroll
            for (int mt = 0; mt < 4; mt++)
                #pragma unroll
                for (int nt = 0; nt < 4; nt++)
                    mma_bf16(acc[mt][nt], ah[mt], bh[nt >> 1][nt & 1], bh[nt >> 1][(nt & 1) + 2]);
            #pragma unroll
            for (int mt = 0; mt < 4; mt++)
                ldsm_x4(aB + mt * 16 * LDAB + 64 + j * 32,
                        al[mt][0], al[mt][1], al[mt][2], al[mt][3]);
            #pragma unroll
            for (int p = 0; p < 2; p++)
                ldsm_x4(bB + p * 16 * LDAB + 64 + j * 32,
                        bl[p][0], bl[p][1], bl[p][2], bl[p][3]);
            #pragma unroll
            for (int mt = 0; mt < 4; mt++)
                #pragma unroll
                for (int nt = 0; nt < 4; nt++)
                    mma_bf16(acc[mt][nt], ah[mt], bl[nt >> 1][nt & 1], bl[nt >> 1][(nt & 1) + 2]);
            #pragma unroll
            for (int mt = 0; mt < 4; mt++)
                #pragma unroll
                for (int nt = 0; nt < 4; nt++)
                    mma_bf16(acc[mt][nt], al[mt], bh[nt >> 1][nt & 1], bh[nt >> 1][(nt & 1) + 2]);
        }
    }

    int qrow = lane >> 2, qcol = (lane & 3) * 2;
    #pragma unroll
    for (int mt = 0; mt < 4; mt++) {
        #pragma unroll
        for (int half = 0; half < 2; half++) {
            int m = wm + mt * 16 + qrow + 8 * half;
            if (m >= rows) continue;
            size_t orow = (size_t)(p0 + m) * F_FF + c0;
            #pragma unroll
            for (int nt = 0; nt < 4; nt++) {
                int nl = wn + nt * 8 + qcol;
                float v0 = gelu_f(acc[mt][nt][2 * half]     + s_bias[nl]);
                float v1 = gelu_f(acc[mt][nt][2 * half + 1] + s_bias[nl + 1]);
                __nv_bfloat16 h0 = __float2bfloat16(v0), h1 = __float2bfloat16(v1);
                __nv_bfloat16 l0 = __float2bfloat16(v0 - __bfloat162float(h0));
                __nv_bfloat16 l1 = __float2bfloat16(v1 - __bfloat162float(h1));
                __nv_bfloat162 ph, pl;
                ph.x = h0; ph.y = h1; pl.x = l0; pl.y = l1;
                *(__nv_bfloat162*)(g_hid_hi + orow + nl) = ph;
                *(__nv_bfloat162*)(g_hid_lo + orow + nl) = pl;
            }
        }
    }
}

// GEMM2 (split-K=2, fused combine): atomicAdd w*(y + b2[q==0]) directly into out.
__global__ __launch_bounds__(256, 2) void gemm2_mma(const float* __restrict__ b2,
                                                    float* __restrict__ out) {
    int tile = blockIdx.y;
    int rows = g_tile_rows[tile];
    if (rows == 0) return;
    int e = g_tile_e[tile], p0 = g_tile_p0[tile];
    int c0 = (blockIdx.x % (D_MODEL / BN)) * BN;
    int kq = blockIdx.x / (D_MODEL / BN);

    extern __shared__ char dyn[];
    int*   s_tok  = (int*)(dyn + STOK_OFF);
    float* s_w    = (float*)(dyn + SW_OFF);
    float* s_bias = (float*)(dyn + SBIAS_OFF);

    int t = threadIdx.x, wid = t >> 5, lane = t & 31;
    if (t < BM) {
        int rr = (t < rows) ? t : (rows - 1);
        s_tok[t] = g_tok[p0 + rr];
        s_w[t]   = g_wass[p0 + rr];
        s_bias[t] = kq ? 0.0f : b2[(size_t)e * D_MODEL + c0 + t];
    }
    __syncthreads();

    uint32_t sb = smem_u32(dyn);
    uint32_t sA[3] = {sb, sb + SA_ST, sb + 2 * SA_ST};
    uint32_t sB[3] = {sb + 3 * SA_ST, sb + 4 * SA_ST, sb + 5 * SA_ST};

    auto loadStage = [&](int kt, int st) {
        int kk = kt * BK;
        const __nv_bfloat16* Ah = g_hid_hi + (size_t)p0 * F_FF + kk;
        const __nv_bfloat16* Al = g_hid_lo + (size_t)p0 * F_FF + kk;
        const __nv_bfloat16* Bh = g_w2T_hi + ((size_t)e * D_MODEL + c0) * F_FF + kk;
        const __nv_bfloat16* Bl = g_w2T_lo + ((size_t)e * D_MODEL + c0) * F_FF + kk;
        #pragma unroll
        for (int it = 0; it < 4; it++) {
            int idx = t + it * 256;
            int row = idx >> 3, c = idx & 7;
            const __nv_bfloat16* src = (c < 4)
                ? Ah + (size_t)row * F_FF + c * 8
                : Al + (size_t)row * F_FF + (c - 4) * 8;
            CP_ASYNC16(sA[st] + row * LDAB + ((c < 4) ? c * 16 : 64 + (c - 4) * 16), src);
        }
        #pragma unroll
        for (int it = 0; it < 4; it++) {
            int idx = t + it * 256;
            int row = idx >> 3, c = idx & 7;
            const __nv_bfloat16* src = (c < 4)
                ? Bh + (size_t)row * F_FF + c * 8
                : Bl + (size_t)row * F_FF + (c - 4) * 8;
            CP_ASYNC16(sB[st] + row * LDAB + ((c < 4) ? c * 16 : 64 + (c - 4) * 16), src);
        }
        CP_COMMIT();
    };

    int wm = (wid >> 2) * 64, wn = (wid & 3) * 32;
    uint32_t aOff = (uint32_t)((wm + (lane & 15)) * LDAB + (lane >> 4) * 16);
    uint32_t bOff = (uint32_t)((wn + (lane & 15)) * LDAB + (lane >> 4) * 16);

    float acc[4][4][4];
    #pragma unroll
    for (int i = 0; i < 4; i++)
        #pragma unroll
        for (int j = 0; j < 4; j++)
            #pragma unroll
            for (int r = 0; r < 4; r++) acc[i][j][r] = 0.0f;

    const int KT_Q = (F_FF / BK) / KSPLIT;   // 32
    int kbase = kq * KT_Q;
    loadStage(kbase + 0, 0);
    loadStage(kbase + 1, 1);
    #pragma unroll 1
    for (int kt = 0; kt < KT_Q; kt++) {
        if (kt + 1 < KT_Q) { CP_WAIT1(); } else { CP_WAIT0(); }
        __syncthreads();
        if (kt + 2 < KT_Q) loadStage(kbase + kt + 2, (kt + 2) % 3);
        int st = kt % 3;
        uint32_t aB = sA[st] + aOff, bB = sB[st] + bOff;

        #pragma unroll
        for (int j = 0; j < 2; j++) {
            uint32_t ah[4][4], al[4][4], bh[2][4], bl[2][4];
            #pragma unroll
            for (int mt = 0; mt < 4; mt++)
                ldsm_x4(aB + mt * 16 * LDAB + j * 32,
                        ah[mt][0], ah[mt][1], ah[mt][2], ah[mt][3]);
            #pragma unroll
            for (int p = 0; p < 2; p++)
                ldsm_x4(bB + p * 16 * LDAB + j * 32,
                        bh[p][0], bh[p][1], bh[p][2], bh[p][3]);
            #pragma unroll
            for (int mt = 0; mt < 4; mt++)
                #pragma unroll
                for (int nt = 0; nt < 4; nt++)
                    mma_bf16(acc[mt][nt], ah[mt], bh[nt >> 1][nt & 1], bh[nt >> 1][(nt & 1) + 2]);
            #pragma unroll
            for (int mt = 0; mt < 4; mt++)
                ldsm_x4(aB + mt * 16 * LDAB + 64 + j * 32,
                        al[mt][0], al[mt][1], al[mt][2], al[mt][3]);
            #pragma unroll
            for (int p = 0; p < 2; p++)
                ldsm_x4(bB + p * 16 * LDAB + 64 + j * 32,
                        bl[p][0], bl[p][1], bl[p][2], bl[p][3]);
            #pragma unroll
            for (int mt = 0; mt < 4; mt++)
                #pragma unroll
                for (int nt = 0; nt < 4; nt++)
                    mma_bf16(acc[mt][nt], ah[mt], bl[nt >> 1][nt & 1], bl[nt >> 1][(nt & 1) + 2]);
            #pragma unroll
            for (int mt = 0; mt < 4; mt++)
                #pragma unroll
                for (int nt = 0; nt < 4; nt++)
                    mma_bf16(acc[mt][nt], al[mt], bh[nt >> 1][nt & 1], bh[nt >> 1][(nt & 1) + 2]);
        }
    }

    int qrow = lane >> 2, qcol = (lane & 3) * 2;
    #pragma unroll
    for (int mt = 0; mt < 4; mt++) {
        #pragma unroll
        for (int half = 0; half < 2; half++) {
            int m = wm + mt * 16 + qrow + 8 * half;
            if (m >= rows) continue;
            int   n = s_tok[m];
            float w = s_w[m];
            float* orow = out + (size_t)n * D_MODEL + c0;
            #pragma unroll
            for (int nt = 0; nt < 4; nt++) {
                int nl = wn + nt * 8 + qcol;
                atomicAdd(orow + nl,     w * (acc[mt][nt][2 * half]     + s_bias[nl]));
                atomicAdd(orow + nl + 1, w * (acc[mt][nt][2 * half + 1] + s_bias[nl + 1]));
            }
        }
    }
}

// ---------------- launch ----------------
extern "C" void kernel_launch(void* const* d_in, const int* in_sizes, int n_in,
                              void* d_out, int out_size) {
    const float* h_t    = (const float*)d_in[0];
    const float* gate_w = (const float*)d_in[1];
    const float* w1     = (const float*)d_in[2];
    const float* b1     = (const float*)d_in[3];
    const float* w2     = (const float*)d_in[4];
    const float* b2     = (const float*)d_in[5];
    float* out = (float*)d_out;

    cudaFuncSetAttribute(gemm1_mma, cudaFuncAttributeMaxDynamicSharedMemorySize, SMEM_BYTES);
    cudaFuncSetAttribute(gemm2_mma, cudaFuncAttributeMaxDynamicSharedMemorySize, SMEM_BYTES);

    cudaMemsetAsync(out, 0, OUT_LOGITS * sizeof(float));   // zero hidden-state region
    init_kernel<<<1, 32>>>();
    prep_kernel<<<NB_GATE + NB_W1T + NB_W2T, 256>>>(h_t, gate_w, w1, w2, out);
    finalize_kernel<<<1, 32>>>(out);
    scatter_kernel<<<N_TOK / 256, 256>>>();
    gemm1_mma<<<dim3(F_FF / BN, NT_TILES), 256, SMEM_BYTES>>>(b1);
    gemm2_mma<<<dim3((D_MODEL / BN) * KSPLIT, NT_TILES), 256, SMEM_BYTES>>>(b2, out);
}

// round 17
// speedup vs baseline: 1.0113x; 1.0113x over previous
#include <cuda_runtime.h>
#include <cuda_bf16.h>
#include <math.h>
#include <stdint.h>

#define D_MODEL 512
#define F_FF    2048
#define N_EXP   8
#define N_TOK   8192
#define N_ASSIGN (N_TOK * 2)
#define NT_TILES 160
#define BM 128
#define BN 128
#define BK 32            // K elems per stage (each row carries hi+lo limbs)
#define LDAB 144         // smem row: 64B hi | 64B lo | 16B pad

#define SA_ST (BM * LDAB)                 // 18432
#define STOK_OFF  (6 * SA_ST)             // 110592 (3 A stages + 3 B stages)
#define SBIAS_OFF (STOK_OFF + 512)
#define SMEM_BYTES (SBIAS_OFF + 512)      // 111616

// prep block partition
#define NB_GATE 1024
#define NB_W1T  8192
#define NB_W2T  8192
#define KSPLIT  2

#define OUT_LOGITS ((size_t)N_TOK * D_MODEL)
#define OUT_PROBS  (OUT_LOGITS + (size_t)N_TOK * N_EXP)
#define OUT_Z      (OUT_PROBS + (size_t)N_TOK * N_EXP)
#define OUT_LB     (OUT_Z + 1)
#define OUT_LOAD   (OUT_LB + 1)
#define OUT_CNT    (OUT_LOAD + N_EXP)

// ---------------- static scratch ----------------
__device__ __nv_bfloat16 g_tok_hi[N_TOK * D_MODEL];
__device__ __nv_bfloat16 g_tok_lo[N_TOK * D_MODEL];
__device__ __nv_bfloat16 g_w1T_hi[N_EXP * F_FF * D_MODEL];   // [E, F, D] K-major
__device__ __nv_bfloat16 g_w1T_lo[N_EXP * F_FF * D_MODEL];
__device__ __nv_bfloat16 g_w2T_hi[N_EXP * D_MODEL * F_FF];   // [E, D, F] K-major
__device__ __nv_bfloat16 g_w2T_lo[N_EXP * D_MODEL * F_FF];
__device__ __nv_bfloat16 g_hid_hi[(N_ASSIGN + BM) * F_FF];
__device__ __nv_bfloat16 g_hid_lo[(N_ASSIGN + BM) * F_FF];
__device__ float g_yp[KSPLIT][(size_t)(N_ASSIGN + BM) * D_MODEL];
__device__ int   g_tok[N_ASSIGN + BM];
__device__ int   g_pos[N_ASSIGN];
__device__ int   g_topk_idx[N_ASSIGN];
__device__ float g_topk_w[N_ASSIGN];
__device__ int   g_cnt[N_EXP];
__device__ int   g_cursor[N_EXP];
__device__ float g_zsum;
__device__ float g_loadsum[N_EXP];
__device__ int   g_tile_e[NT_TILES];
__device__ int   g_tile_p0[NT_TILES];
__device__ int   g_tile_rows[NT_TILES];

// ---------------- PTX helpers (baseline ISA only) ----------------
__device__ __forceinline__ uint32_t smem_u32(const void* p) {
    uint32_t a;
    asm("{ .reg .u64 t; cvta.to.shared.u64 t, %1; cvt.u32.u64 %0, t; }" : "=r"(a) : "l"(p));
    return a;
}
#define CP_ASYNC16(dst, src) \
    asm volatile("cp.async.cg.shared.global [%0], [%1], 16;" :: "r"(dst), "l"(src) : "memory")
#define CP_COMMIT() asm volatile("cp.async.commit_group;" ::: "memory")
#define CP_WAIT1()  asm volatile("cp.async.wait_group 1;" ::: "memory")
#define CP_WAIT0()  asm volatile("cp.async.wait_group 0;" ::: "memory")

__device__ __forceinline__ void ldsm_x4(uint32_t addr, uint32_t& r0, uint32_t& r1,
                                        uint32_t& r2, uint32_t& r3) {
    asm volatile("ldmatrix.sync.aligned.m8n8.x4.shared.b16 {%0,%1,%2,%3}, [%4];"
        : "=r"(r0), "=r"(r1), "=r"(r2), "=r"(r3) : "r"(addr));
}
__device__ __forceinline__ void mma_bf16(float* d, const uint32_t* a,
                                         uint32_t b0, uint32_t b1) {
    asm volatile(
        "mma.sync.aligned.m16n8k16.row.col.f32.bf16.bf16.f32 "
        "{%0,%1,%2,%3}, {%4,%5,%6,%7}, {%8,%9}, {%0,%1,%2,%3};"
        : "+f"(d[0]), "+f"(d[1]), "+f"(d[2]), "+f"(d[3])
        : "r"(a[0]), "r"(a[1]), "r"(a[2]), "r"(a[3]), "r"(b0), "r"(b1));
}
// fast gelu via MUFU ex2/rcp; rel err ~1e-6
__device__ __forceinline__ float gelu_f(float x) {
    const float c = 0.7978845608028654f;
    float u = c * (x + 0.044715f * x * x * x);
    float e = __expf(2.0f * u);
    float t = 1.0f - __fdividef(2.0f, e + 1.0f);
    return 0.5f * x * (1.0f + t);
}

// ---------------- init ----------------
__global__ void init_kernel() {
    int t = threadIdx.x;
    if (t < N_EXP) { g_cnt[t] = 0; g_loadsum[t] = 0.0f; }
    if (t == 0) g_zsum = 0.0f;
}

// ---------------- shared transpose+split body ----------------
__device__ __forceinline__ void transpose_split_part(
    float (*tile)[33], const float* __restrict__ in,
    __nv_bfloat16* __restrict__ out_hi, __nv_bfloat16* __restrict__ out_lo,
    int R, int C, int e, int c0, int r0, int tx, int ty)
{
    const float* src = in + (size_t)e * R * C;
    #pragma unroll
    for (int i = ty; i < 32; i += 8)
        tile[i][tx] = src[(size_t)(r0 + i) * C + c0 + tx];
    __syncthreads();
    __nv_bfloat16* dh = out_hi + (size_t)e * R * C;
    __nv_bfloat16* dl = out_lo + (size_t)e * R * C;
    #pragma unroll
    for (int i = ty; i < 32; i += 8) {
        float v = tile[tx][i];
        __nv_bfloat16 h = __float2bfloat16(v);
        __nv_bfloat16 l = __float2bfloat16(v - __bfloat162float(h));
        dh[(size_t)(c0 + i) * R + r0 + tx] = h;
        dl[(size_t)(c0 + i) * R + r0 + tx] = l;
    }
}

// ================ prep: gating(+stats) + token split + both weight transposes ========
__global__ __launch_bounds__(256) void prep_kernel(
    const float* __restrict__ tokens, const float* __restrict__ gate_w,
    const float* __restrict__ w1, const float* __restrict__ w2,
    float* __restrict__ out)
{
    __shared__ __align__(16) char sbuf[16384];
    __shared__ float s_load[N_EXP];
    __shared__ int   s_cnt[N_EXP];
    __shared__ float s_z;
    int b = blockIdx.x;
    int t = threadIdx.x;

    if (b >= NB_GATE) {
        float (*tile)[33] = (float(*)[33])sbuf;
        int tx = t & 31, ty = t >> 5;
        if (b < NB_GATE + NB_W1T) {
            int idx = b - NB_GATE;
            int e = idx >> 10, rem = idx & 1023;
            int c0 = (rem & 63) * 32, r0 = (rem >> 6) * 32;
            transpose_split_part(tile, w1, g_w1T_hi, g_w1T_lo, D_MODEL, F_FF, e, c0, r0, tx, ty);
        } else {
            int idx = b - NB_GATE - NB_W1T;
            int e = idx >> 10, rem = idx & 1023;
            int c0 = (rem & 15) * 32, r0 = (rem >> 4) * 32;
            transpose_split_part(tile, w2, g_w2T_hi, g_w2T_lo, F_FF, D_MODEL, e, c0, r0, tx, ty);
        }
        return;
    }

    float* gwT = (float*)sbuf;   // [8][512]
    for (int i = t; i < D_MODEL * N_EXP; i += 256) {
        int d = i >> 3, e = i & 7;
        gwT[e * 512 + d] = gate_w[i];
    }
    if (t < N_EXP) { s_load[t] = 0.0f; s_cnt[t] = 0; }
    if (t == 0) s_z = 0.0f;
    __syncthreads();

    int n0 = b * 8;
    {
        const float4* src = (const float4*)(tokens + (size_t)n0 * D_MODEL);
        size_t obase = (size_t)n0 * D_MODEL;
        for (int i = t; i < 1024; i += 256) {
            float4 v = src[i];
            __nv_bfloat16 h0 = __float2bfloat16(v.x), h1 = __float2bfloat16(v.y);
            __nv_bfloat16 h2 = __float2bfloat16(v.z), h3 = __float2bfloat16(v.w);
            __nv_bfloat16 l0 = __float2bfloat16(v.x - __bfloat162float(h0));
            __nv_bfloat16 l1 = __float2bfloat16(v.y - __bfloat162float(h1));
            __nv_bfloat16 l2 = __float2bfloat16(v.z - __bfloat162float(h2));
            __nv_bfloat16 l3 = __float2bfloat16(v.w - __bfloat162float(h3));
            __nv_bfloat162 ph0, ph1, pl0, pl1;
            ph0.x = h0; ph0.y = h1; ph1.x = h2; ph1.y = h3;
            pl0.x = l0; pl0.y = l1; pl1.x = l2; pl1.y = l3;
            ((__nv_bfloat162*)(g_tok_hi + obase))[2*i]   = ph0;
            ((__nv_bfloat162*)(g_tok_hi + obase))[2*i+1] = ph1;
            ((__nv_bfloat162*)(g_tok_lo + obase))[2*i]   = pl0;
            ((__nv_bfloat162*)(g_tok_lo + obase))[2*i+1] = pl1;
        }
    }

    int warp = t >> 5, lane = t & 31;
    int n = n0 + warp;
    const float* x = tokens + (size_t)n * D_MODEL;

    float acc[8] = {0.f,0.f,0.f,0.f,0.f,0.f,0.f,0.f};
    for (int d = lane; d < D_MODEL; d += 32) {
        float xv = x[d];
        #pragma unroll
        for (int e = 0; e < 8; e++) acc[e] = fmaf(xv, gwT[e * 512 + d], acc[e]);
    }
    #pragma unroll
    for (int e = 0; e < 8; e++) {
        #pragma unroll
        for (int o = 16; o; o >>= 1)
            acc[e] += __shfl_down_sync(0xffffffffu, acc[e], o);
    }

    if (lane == 0) {
        float m = acc[0];
        #pragma unroll
        for (int e = 1; e < 8; e++) m = fmaxf(m, acc[e]);
        float p[8], s = 0.0f;
        #pragma unroll
        for (int e = 0; e < 8; e++) { p[e] = expf(acc[e] - m); s += p[e]; }
        float inv = 1.0f / s;
        #pragma unroll
        for (int e = 0; e < 8; e++) p[e] *= inv;

        float* gl = out + OUT_LOGITS + (size_t)n * N_EXP;
        float* pr = out + OUT_PROBS  + (size_t)n * N_EXP;
        #pragma unroll
        for (int e = 0; e < 8; e++) { gl[e] = acc[e]; pr[e] = p[e]; }

        float lse = m + logf(s);
        atomicAdd(&s_z, lse * lse);
        #pragma unroll
        for (int e = 0; e < 8; e++) atomicAdd(&s_load[e], p[e]);

        int i0 = 0; float m0 = p[0];
        #pragma unroll
        for (int e = 1; e < 8; e++) if (p[e] > m0) { m0 = p[e]; i0 = e; }
        int i1 = (i0 == 0) ? 1 : 0; float m1 = p[i1];
        #pragma unroll
        for (int e = 0; e < 8; e++)
            if (e != i0 && p[e] > m1) { m1 = p[e]; i1 = e; }
        float ws = m0 + m1;
        g_topk_idx[2 * n]     = i0;
        g_topk_idx[2 * n + 1] = i1;
        g_topk_w[2 * n]       = m0 / ws;
        g_topk_w[2 * n + 1]   = m1 / ws;
        atomicAdd(&s_cnt[i0], 1);
        atomicAdd(&s_cnt[i1], 1);
    }
    __syncthreads();
    if (t < N_EXP) {
        atomicAdd(&g_cnt[t], s_cnt[t]);
        atomicAdd(&g_loadsum[t], s_load[t]);
    }
    if (t == 0) atomicAdd(&g_zsum, s_z);
}

// ---------------- finalize ----------------
__global__ void finalize_kernel(float* __restrict__ out) {
    if (threadIdx.x != 0) return;
    int off = 0;
    float lb = 0.0f;
    int tcount = 0;
    for (int e = 0; e < N_EXP; e++) {
        g_cursor[e] = off;
        int cnt = g_cnt[e];
        float load = g_loadsum[e] / (float)N_TOK;
        out[OUT_LOAD + e] = load;
        out[OUT_CNT + e]  = (float)cnt;
        lb += ((float)cnt / (float)N_ASSIGN) * load;
        for (int r = 0; r < cnt; r += BM) {
            g_tile_e[tcount]    = e;
            g_tile_p0[tcount]   = off + r;
            int rem = cnt - r;
            g_tile_rows[tcount] = rem < BM ? rem : BM;
            tcount++;
        }
        off += cnt;
    }
    for (int i = tcount; i < NT_TILES; i++) g_tile_rows[i] = 0;
    out[OUT_LB] = (float)N_EXP * lb;
    out[OUT_Z]  = g_zsum / (float)N_TOK;
}

// ---------------- scatter ----------------
__global__ void scatter_kernel() {
    int n = blockIdx.x * blockDim.x + threadIdx.x;
    if (n >= N_TOK) return;
    #pragma unroll
    for (int k = 0; k < 2; k++) {
        int e = g_topk_idx[2 * n + k];
        int pos = atomicAdd(&g_cursor[e], 1);
        g_tok[pos] = n;
        g_pos[2 * n + k] = pos;
    }
}

// =============== fused-limb warp-MMA GEMMs ===============
// CTA 128x128, 8 warps 2(M)x4(N), warp tile 64x32. BK=32/stage, rows hi|lo|pad.

// GEMM1: hidden = gelu(gather(tokens) @ w1T^T + b1) -> split bf16 hi/lo
__global__ __launch_bounds__(256, 2) void gemm1_mma(const float* __restrict__ b1) {
    int tile = blockIdx.y;
    int rows = g_tile_rows[tile];
    if (rows == 0) return;
    int e = g_tile_e[tile], p0 = g_tile_p0[tile];
    int c0 = blockIdx.x * BN;

    extern __shared__ char dyn[];
    int*   s_tok  = (int*)(dyn + STOK_OFF);
    float* s_bias = (float*)(dyn + SBIAS_OFF);

    int t = threadIdx.x, wid = t >> 5, lane = t & 31;
    if (t < BM) {
        int rr = (t < rows) ? t : (rows - 1);
        s_tok[t]  = g_tok[p0 + rr];
        s_bias[t] = b1[(size_t)e * F_FF + c0 + t];
    }
    __syncthreads();

    uint32_t sb = smem_u32(dyn);
    uint32_t sA[3] = {sb, sb + SA_ST, sb + 2 * SA_ST};
    uint32_t sB[3] = {sb + 3 * SA_ST, sb + 4 * SA_ST, sb + 5 * SA_ST};

    auto loadStage = [&](int kt, int st) {
        int kk = kt * BK;
        #pragma unroll
        for (int it = 0; it < 4; it++) {
            int idx = t + it * 256;
            int row = idx >> 3, c = idx & 7;
            const __nv_bfloat16* src = (c < 4)
                ? g_tok_hi + (size_t)s_tok[row] * D_MODEL + kk + c * 8
                : g_tok_lo + (size_t)s_tok[row] * D_MODEL + kk + (c - 4) * 8;
            CP_ASYNC16(sA[st] + row * LDAB + ((c < 4) ? c * 16 : 64 + (c - 4) * 16), src);
        }
        const __nv_bfloat16* Bh = g_w1T_hi + ((size_t)e * F_FF + c0) * D_MODEL + kk;
        const __nv_bfloat16* Bl = g_w1T_lo + ((size_t)e * F_FF + c0) * D_MODEL + kk;
        #pragma unroll
        for (int it = 0; it < 4; it++) {
            int idx = t + it * 256;
            int row = idx >> 3, c = idx & 7;
            const __nv_bfloat16* src = (c < 4)
                ? Bh + (size_t)row * D_MODEL + c * 8
                : Bl + (size_t)row * D_MODEL + (c - 4) * 8;
            CP_ASYNC16(sB[st] + row * LDAB + ((c < 4) ? c * 16 : 64 + (c - 4) * 16), src);
        }
        CP_COMMIT();
    };

    int wm = (wid >> 2) * 64, wn = (wid & 3) * 32;
    uint32_t aOff = (uint32_t)((wm + (lane & 15)) * LDAB + (lane >> 4) * 16);
    uint32_t bOff = (uint32_t)((wn + (lane & 15)) * LDAB + (lane >> 4) * 16);

    float acc[4][4][4];
    #pragma unroll
    for (int i = 0; i < 4; i++)
        #pragma unroll
        for (int j = 0; j < 4; j++)
            #pragma unroll
            for (int r = 0; r < 4; r++) acc[i][j][r] = 0.0f;

    const int KT = D_MODEL / BK;   // 16
    loadStage(0, 0);
    loadStage(1, 1);
    #pragma unroll 1
    for (int kt = 0; kt < KT; kt++) {
        if (kt + 1 < KT) { CP_WAIT1(); } else { CP_WAIT0(); }
        __syncthreads();
        if (kt + 2 < KT) loadStage(kt + 2, (kt + 2) % 3);
        int st = kt % 3;
        uint32_t aB = sA[st] + aOff, bB = sB[st] + bOff;

        #pragma unroll
        for (int j = 0; j < 2; j++) {          // k16 sub-chunks
            uint32_t ah[4][4], al[4][4], bh[2][4], bl[2][4];
            #pragma unroll
            for (int mt = 0; mt < 4; mt++)
                ldsm_x4(aB + mt * 16 * LDAB + j * 32,
                        ah[mt][0], ah[mt][1], ah[mt][2], ah[mt][3]);
            #pragma unroll
            for (int p = 0; p < 2; p++)
                ldsm_x4(bB + p * 16 * LDAB + j * 32,
                        bh[p][0], bh[p][1], bh[p][2], bh[p][3]);
            #pragma unroll
            for (int mt = 0; mt < 4; mt++)
                #pragma unroll
                for (int nt = 0; nt < 4; nt++)
                    mma_bf16(acc[mt][nt], ah[mt], bh[nt >> 1][nt & 1], bh[nt >> 1][(nt & 1) + 2]);
            #pragma unroll
            for (int mt = 0; mt < 4; mt++)
                ldsm_x4(aB + mt * 16 * LDAB + 64 + j * 32,
                        al[mt][0], al[mt][1], al[mt][2], al[mt][3]);
            #pragma unroll
            for (int p = 0; p < 2; p++)
                ldsm_x4(bB + p * 16 * LDAB + 64 + j * 32,
                        bl[p][0], bl[p][1], bl[p][2], bl[p][3]);
            #pragma unroll
            for (int mt = 0; mt < 4; mt++)
                #pragma unroll
                for (int nt = 0; nt < 4; nt++)
                    mma_bf16(acc[mt][nt], ah[mt], bl[nt >> 1][nt & 1], bl[nt >> 1][(nt & 1) + 2]);
            #pragma unroll
            for (int mt = 0; mt < 4; mt++)
                #pragma unroll
                for (int nt = 0; nt < 4; nt++)
                    mma_bf16(acc[mt][nt], al[mt], bh[nt >> 1][nt & 1], bh[nt >> 1][(nt & 1) + 2]);
        }
    }

    int qrow = lane >> 2, qcol = (lane & 3) * 2;
    #pragma unroll
    for (int mt = 0; mt < 4; mt++) {
        #pragma unroll
        for (int half = 0; half < 2; half++) {
            int m = wm + mt * 16 + qrow + 8 * half;
            if (m >= rows) continue;
            size_t orow = (size_t)(p0 + m) * F_FF + c0;
            #pragma unroll
            for (int nt = 0; nt < 4; nt++) {
                int nl = wn + nt * 8 + qcol;
                float v0 = gelu_f(acc[mt][nt][2 * half]     + s_bias[nl]);
                float v1 = gelu_f(acc[mt][nt][2 * half + 1] + s_bias[nl + 1]);
                __nv_bfloat16 h0 = __float2bfloat16(v0), h1 = __float2bfloat16(v1);
                __nv_bfloat16 l0 = __float2bfloat16(v0 - __bfloat162float(h0));
                __nv_bfloat16 l1 = __float2bfloat16(v1 - __bfloat162float(h1));
                __nv_bfloat162 ph, pl;
                ph.x = h0; ph.y = h1; pl.x = l0; pl.y = l1;
                *(__nv_bfloat162*)(g_hid_hi + orow + nl) = ph;
                *(__nv_bfloat162*)(g_hid_lo + orow + nl) = pl;
            }
        }
    }
}

// GEMM2 (split-K=2): y[q] = hidden[:, Kq] @ w2T^T (+ b2 on q==0)
__global__ __launch_bounds__(256, 2) void gemm2_mma(const float* __restrict__ b2) {
    int tile = blockIdx.y;
    int rows = g_tile_rows[tile];
    if (rows == 0) return;
    int e = g_tile_e[tile], p0 = g_tile_p0[tile];
    int c0 = (blockIdx.x % (D_MODEL / BN)) * BN;
    int kq = blockIdx.x / (D_MODEL / BN);

    extern __shared__ char dyn[];
    float* s_bias = (float*)(dyn + SBIAS_OFF);

    int t = threadIdx.x, wid = t >> 5, lane = t & 31;
    if (t < BN) s_bias[t] = kq ? 0.0f : b2[(size_t)e * D_MODEL + c0 + t];
    __syncthreads();

    uint32_t sb = smem_u32(dyn);
    uint32_t sA[3] = {sb, sb + SA_ST, sb + 2 * SA_ST};
    uint32_t sB[3] = {sb + 3 * SA_ST, sb + 4 * SA_ST, sb + 5 * SA_ST};

    auto loadStage = [&](int kt, int st) {
        int kk = kt * BK;
        const __nv_bfloat16* Ah = g_hid_hi + (size_t)p0 * F_FF + kk;
        const __nv_bfloat16* Al = g_hid_lo + (size_t)p0 * F_FF + kk;
        const __nv_bfloat16* Bh = g_w2T_hi + ((size_t)e * D_MODEL + c0) * F_FF + kk;
        const __nv_bfloat16* Bl = g_w2T_lo + ((size_t)e * D_MODEL + c0) * F_FF + kk;
        #pragma unroll
        for (int it = 0; it < 4; it++) {
            int idx = t + it * 256;
            int row = idx >> 3, c = idx & 7;
            const __nv_bfloat16* src = (c < 4)
                ? Ah + (size_t)row * F_FF + c * 8
                : Al + (size_t)row * F_FF + (c - 4) * 8;
            CP_ASYNC16(sA[st] + row * LDAB + ((c < 4) ? c * 16 : 64 + (c - 4) * 16), src);
        }
        #pragma unroll
        for (int it = 0; it < 4; it++) {
            int idx = t + it * 256;
            int row = idx >> 3, c = idx & 7;
            const __nv_bfloat16* src = (c < 4)
                ? Bh + (size_t)row * F_FF + c * 8
                : Bl + (size_t)row * F_FF + (c - 4) * 8;
            CP_ASYNC16(sB[st] + row * LDAB + ((c < 4) ? c * 16 : 64 + (c - 4) * 16), src);
        }
        CP_COMMIT();
    };

    int wm = (wid >> 2) * 64, wn = (wid & 3) * 32;
    uint32_t aOff = (uint32_t)((wm + (lane & 15)) * LDAB + (lane >> 4) * 16);
    uint32_t bOff = (uint32_t)((wn + (lane & 15)) * LDAB + (lane >> 4) * 16);

    float acc[4][4][4];
    #pragma unroll
    for (int i = 0; i < 4; i++)
        #pragma unroll
        for (int j = 0; j < 4; j++)
            #pragma unroll
            for (int r = 0; r < 4; r++) acc[i][j][r] = 0.0f;

    const int KT_Q = (F_FF / BK) / KSPLIT;   // 32
    int kbase = kq * KT_Q;
    loadStage(kbase + 0, 0);
    loadStage(kbase + 1, 1);
    #pragma unroll 1
    for (int kt = 0; kt < KT_Q; kt++) {
        if (kt + 1 < KT_Q) { CP_WAIT1(); } else { CP_WAIT0(); }
        __syncthreads();
        if (kt + 2 < KT_Q) loadStage(kbase + kt + 2, (kt + 2) % 3);
        int st = kt % 3;
        uint32_t aB = sA[st] + aOff, bB = sB[st] + bOff;

        #pragma unroll
        for (int j = 0; j < 2; j++) {
            uint32_t ah[4][4], al[4][4], bh[2][4], bl[2][4];
            #pragma unroll
            for (int mt = 0; mt < 4; mt++)
                ldsm_x4(aB + mt * 16 * LDAB + j * 32,
                        ah[mt][0], ah[mt][1], ah[mt][2], ah[mt][3]);
            #pragma unroll
            for (int p = 0; p < 2; p++)
                ldsm_x4(bB + p * 16 * LDAB + j * 32,
                        bh[p][0], bh[p][1], bh[p][2], bh[p][3]);
            #pragma unroll
            for (int mt = 0; mt < 4; mt++)
                #pragma unroll
                for (int nt = 0; nt < 4; nt++)
                    mma_bf16(acc[mt][nt], ah[mt], bh[nt >> 1][nt & 1], bh[nt >> 1][(nt & 1) + 2]);
            #pragma unroll
            for (int mt = 0; mt < 4; mt++)
                ldsm_x4(aB + mt * 16 * LDAB + 64 + j * 32,
                        al[mt][0], al[mt][1], al[mt][2], al[mt][3]);
            #pragma unroll
            for (int p = 0; p < 2; p++)
                ldsm_x4(bB + p * 16 * LDAB + 64 + j * 32,
                        bl[p][0], bl[p][1], bl[p][2], bl[p][3]);
            #pragma unroll
            for (int mt = 0; mt < 4; mt++)
                #pragma unroll
                for (int nt = 0; nt < 4; nt++)
                    mma_bf16(acc[mt][nt], ah[mt], bl[nt >> 1][nt & 1], bl[nt >> 1][(nt & 1) + 2]);
            #pragma unroll
            for (int mt = 0; mt < 4; mt++)
                #pragma unroll
                for (int nt = 0; nt < 4; nt++)
                    mma_bf16(acc[mt][nt], al[mt], bh[nt >> 1][nt & 1], bh[nt >> 1][(nt & 1) + 2]);
        }
    }

    float* yout = g_yp[kq];
    int qrow = lane >> 2, qcol = (lane & 3) * 2;
    #pragma unroll
    for (int mt = 0; mt < 4; mt++) {
        #pragma unroll
        for (int half = 0; half < 2; half++) {
            int m = wm + mt * 16 + qrow + 8 * half;
            if (m >= rows) continue;
            size_t orow = (size_t)(p0 + m) * D_MODEL + c0;
            #pragma unroll
            for (int nt = 0; nt < 4; nt++) {
                int nl = wn + nt * 8 + qcol;
                float2 v;
                v.x = acc[mt][nt][2 * half]     + s_bias[nl];
                v.y = acc[mt][nt][2 * half + 1] + s_bias[nl + 1];
                *(float2*)(yout + orow + nl) = v;
            }
        }
    }
}

// ---------------- combine: out = w0*sum_q(yq[p0]) + w1*sum_q(yq[p1]) ----------------
// 256 threads handle 2 tokens per block (grid halved vs 1-token blocks).
__global__ __launch_bounds__(256) void combine_kernel(float* __restrict__ out) {
    int n = blockIdx.x * 2 + (threadIdx.x >> 7);
    int d = (threadIdx.x & 127) * 4;
    int pa = g_pos[2 * n], pb = g_pos[2 * n + 1];
    float w0 = g_topk_w[2 * n], w1 = g_topk_w[2 * n + 1];
    float4 sa = make_float4(0.f, 0.f, 0.f, 0.f);
    float4 sbv = make_float4(0.f, 0.f, 0.f, 0.f);
    #pragma unroll
    for (int q = 0; q < KSPLIT; q++) {
        float4 ya = *(const float4*)(g_yp[q] + (size_t)pa * D_MODEL + d);
        float4 yb = *(const float4*)(g_yp[q] + (size_t)pb * D_MODEL + d);
        sa.x += ya.x; sa.y += ya.y; sa.z += ya.z; sa.w += ya.w;
        sbv.x += yb.x; sbv.y += yb.y; sbv.z += yb.z; sbv.w += yb.w;
    }
    float4 r;
    r.x = w0 * sa.x + w1 * sbv.x;
    r.y = w0 * sa.y + w1 * sbv.y;
    r.z = w0 * sa.z + w1 * sbv.z;
    r.w = w0 * sa.w + w1 * sbv.w;
    *(float4*)(out + (size_t)n * D_MODEL + d) = r;
}

// ---------------- launch ----------------
extern "C" void kernel_launch(void* const* d_in, const int* in_sizes, int n_in,
                              void* d_out, int out_size) {
    const float* h_t    = (const float*)d_in[0];
    const float* gate_w = (const float*)d_in[1];
    const float* w1     = (const float*)d_in[2];
    const float* b1     = (const float*)d_in[3];
    const float* w2     = (const float*)d_in[4];
    const float* b2     = (const float*)d_in[5];
    float* out = (float*)d_out;

    cudaFuncSetAttribute(gemm1_mma, cudaFuncAttributeMaxDynamicSharedMemorySize, SMEM_BYTES);
    cudaFuncSetAttribute(gemm2_mma, cudaFuncAttributeMaxDynamicSharedMemorySize, SMEM_BYTES);

    init_kernel<<<1, 32>>>();
    prep_kernel<<<NB_GATE + NB_W1T + NB_W2T, 256>>>(h_t, gate_w, w1, w2, out);
    finalize_kernel<<<1, 32>>>(out);
    scatter_kernel<<<N_TOK / 256, 256>>>();
    gemm1_mma<<<dim3(F_FF / BN, NT_TILES), 256, SMEM_BYTES>>>(b1);
    gemm2_mma<<<dim3((D_MODEL / BN) * KSPLIT, NT_TILES), 256, SMEM_BYTES>>>(b2);
    combine_kernel<<<N_TOK / 2, 256>>>(out);
}